// round 8
// baseline (speedup 1.0000x reference)
#include <cuda_runtime.h>
#include <cuda_bf16.h>
#include <cstdint>

typedef unsigned int u32;
typedef unsigned long long u64;

#define BB   8
#define CIN  512
#define MIDC 128
#define NNE  2304
#define SCALE_S 0.08838834764831845f

// ---------------- scratch layout (bytes) ----------------
#define XT_SZ   ((size_t)3*BB*NNE*CIN*2)
#define FT_ONE  ((size_t)BB*NNE*MIDC*2)
#define G_SZ    ((size_t)2*BB*MIDC*NNE*4)
#define GN_SZ   ((size_t)2*BB*MIDC*NNE*2)
#define ET_SZ   ((size_t)2*BB*NNE*NNE*2)
#define Z_SZ    ((size_t)2*BB*NNE*4)
#define OT_SZ   ((size_t)2*BB*NNE*MIDC*2)
#define WC_SZ   ((size_t)6*65536*2)

#define XT_OFF  0ull
#define FT_OFF  (XT_OFF + XT_SZ)
#define G_OFF   (FT_OFF + 3*FT_ONE)
#define GN_OFF  (G_OFF + G_SZ)
#define ET_OFF  (GN_OFF + GN_SZ)
#define Z_OFF   (ET_OFF + ET_SZ)
#define OT_OFF  (Z_OFF + Z_SZ)
#define WC_OFF  (OT_OFF + OT_SZ)
#define TOTAL_SCRATCH (WC_OFF + WC_SZ)

__device__ __align__(1024) char d_scratch[TOTAL_SCRATCH];

// ---------------- HMMA building blocks ----------------
__device__ __forceinline__ u32 pack_bf16(float lo, float hi) {
    u32 r; asm("cvt.rn.bf16x2.f32 %0, %1, %2;" : "=r"(r) : "f"(hi), "f"(lo)); return r;
}
__device__ __forceinline__ void cpasync16(u32 saddr, const void* g) {
    asm volatile("cp.async.cg.shared.global [%0], [%1], 16;" :: "r"(saddr), "l"(g));
}
#define CP_COMMIT() asm volatile("cp.async.commit_group;" ::: "memory")

__device__ __forceinline__ void ldsm_x4(u32 a, u32& r0, u32& r1, u32& r2, u32& r3) {
    asm volatile("ldmatrix.sync.aligned.m8n8.x4.shared.b16 {%0,%1,%2,%3}, [%4];"
                 : "=r"(r0), "=r"(r1), "=r"(r2), "=r"(r3) : "r"(a));
}
__device__ __forceinline__ void mma16816(float c[4], const u32 a[4], u32 b0, u32 b1) {
    asm volatile("mma.sync.aligned.m16n8k16.row.col.f32.bf16.bf16.f32 "
                 "{%0,%1,%2,%3}, {%4,%5,%6,%7}, {%8,%9}, {%0,%1,%2,%3};"
                 : "+f"(c[0]), "+f"(c[1]), "+f"(c[2]), "+f"(c[3])
                 : "r"(a[0]), "r"(a[1]), "r"(a[2]), "r"(a[3]), "r"(b0), "r"(b1));
}

// Tile: 128 rows x 64 bf16 (128 B/row). Swizzle cc = c ^ (r&7) — conflict-free.
#define BK 64
#define TILE_B (128 * BK * 2)   // 16384 bytes

__device__ __forceinline__ u32 sw64(int r, int ch) {
    return (u32)(r * 128 + ((ch ^ (r & 7)) << 4));
}

// 128 threads: thread tid fills row tid (8 x 16B chunks)
__device__ __forceinline__ void tile_load(u32 sdst, const __nv_bfloat16* src,
                                          size_t pitch, int k0, int tid) {
    const char* g = (const char*)(src + (size_t)tid * pitch + k0);
#pragma unroll
    for (int c = 0; c < 8; c++)
        cpasync16(sdst + sw64(tid, c), g + c * 16);
}

// CTA 128x128 GEMM: acc += A(128 x Kd, k-major) · B(128 x Kd, k-major)^T
// 128 threads, 4 warps 2(M) x 2(N), warp tile 64x64, BK=64 double-buffered.
__device__ __forceinline__ void hmma_gemm(
    u32 sA, u32 sB,
    const __nv_bfloat16* __restrict__ A, size_t pA,
    const __nv_bfloat16* __restrict__ B, size_t pB,
    int Kd, int tid, float acc[4][8][4])
{
#pragma unroll
    for (int i = 0; i < 4; i++)
#pragma unroll
        for (int j = 0; j < 8; j++)
#pragma unroll
            for (int e = 0; e < 4; e++) acc[i][j][e] = 0.f;

    const int lane = tid & 31, wid = tid >> 5;
    const int wm = wid & 1, wn = wid >> 1;

    tile_load(sA, A, pA, 0, tid);
    tile_load(sB, B, pB, 0, tid);
    CP_COMMIT();

    const int T = Kd / BK;
    for (int t = 0; t < T; t++) {
        const int cur = t & 1;
        if (t + 1 < T) {
            tile_load(sA + (cur ^ 1) * TILE_B, A, pA, (t + 1) * BK, tid);
            tile_load(sB + (cur ^ 1) * TILE_B, B, pB, (t + 1) * BK, tid);
            CP_COMMIT();
            asm volatile("cp.async.wait_group 1;" ::: "memory");
        } else {
            asm volatile("cp.async.wait_group 0;" ::: "memory");
        }
        __syncthreads();
        const u32 abuf = sA + cur * TILE_B;
        const u32 bbuf = sB + cur * TILE_B;
#pragma unroll
        for (int k16 = 0; k16 < 4; k16++) {
            u32 a[4][4];
#pragma unroll
            for (int f = 0; f < 4; f++) {
                int row = wm * 64 + f * 16 + (lane & 15);
                int ch  = k16 * 2 + (lane >> 4);
                ldsm_x4(abuf + sw64(row, ch), a[f][0], a[f][1], a[f][2], a[f][3]);
            }
            u32 b[8][2];
#pragma unroll
            for (int p = 0; p < 4; p++) {
                int row = wn * 64 + p * 16 + ((lane & 16) >> 1) + (lane & 7);
                int ch  = k16 * 2 + ((lane >> 3) & 1);
                ldsm_x4(bbuf + sw64(row, ch), b[2 * p][0], b[2 * p][1],
                        b[2 * p + 1][0], b[2 * p + 1][1]);
            }
#pragma unroll
            for (int mf = 0; mf < 4; mf++)
#pragma unroll
                for (int nf = 0; nf < 8; nf++)
                    mma16816(acc[mf][nf], a[mf], b[nf][0], b[nf][1]);
        }
        __syncthreads();
    }
}

#define SMEM_DYN (4 * TILE_B)   // 64 KB

// ============================ SIMT prep ============================
__global__ __launch_bounds__(256) void transpose_x(
    const float* __restrict__ x, const float* __restrict__ x_v,
    const float* __restrict__ x_h, __nv_bfloat16* __restrict__ xT)
{
    __shared__ float t[32][33];
    int z = blockIdx.z, tt = z >> 3, b = z & 7;
    const float* src = (tt == 0) ? x : (tt == 1 ? x_v : x_h);
    int n0 = blockIdx.x * 32, c0 = blockIdx.y * 32;
    int tx = threadIdx.x & 31, ty8 = threadIdx.x >> 5;
#pragma unroll
    for (int i = 0; i < 4; i++)
        t[ty8 + i * 8][tx] = src[((size_t)b * CIN + c0 + ty8 + i * 8) * NNE + n0 + tx];
    __syncthreads();
#pragma unroll
    for (int i = 0; i < 4; i++)
        xT[(((size_t)tt * BB + b) * NNE + n0 + ty8 + i * 8) * CIN + c0 + tx] =
            __float2bfloat16(t[tx][ty8 + i * 8]);
}

struct WC6 { const float* s[6]; };
__global__ __launch_bounds__(256) void conv_weights(WC6 w, __nv_bfloat16* __restrict__ dst,
                                                    float* __restrict__ Z)
{
    int idx = blockIdx.x * 256 + threadIdx.x;
    int t = idx >> 16, i = idx & 65535;
    dst[(size_t)t * 65536 + i] = __float2bfloat16(w.s[t][i]);
    if (idx < 2 * BB * NNE) Z[idx] = 0.f;
}

__global__ __launch_bounds__(256) void gnorm(
    const float* __restrict__ g, const float* __restrict__ Z, __nv_bfloat16* __restrict__ gn)
{
    size_t idx = (size_t)blockIdx.x * 256 + threadIdx.x;
    int n = (int)(idx % NNE);
    size_t sb = idx / ((size_t)NNE * MIDC);
    gn[idx] = __float2bfloat16(g[idx] * __frcp_rn(Z[sb * NNE + n]));
}

// ============================ HMMA kernels (128 threads) ============================

// f[o][b][n][m] = relu(BN(xT·W^T)). grid (18, BB, 3). rows=n, cols=m.
__global__ __launch_bounds__(128, 2) void k_fconv(
    const __nv_bfloat16* __restrict__ xT, const __nv_bfloat16* __restrict__ Wc,
    const float* __restrict__ ba, const float* __restrict__ ga, const float* __restrict__ ta,
    const float* __restrict__ bv, const float* __restrict__ gv, const float* __restrict__ tv,
    __nv_bfloat16* __restrict__ ft)
{
    extern __shared__ char dsm[];
    __shared__ float sS[128], sC[128];
    int tid = threadIdx.x, lane = tid & 31, wid = tid >> 5;
    int wm = wid & 1, wn = wid >> 1;
    int nt = blockIdx.x, b = blockIdx.y, o = blockIdx.z;

    {
        const float* bias  = (o == 0) ? ba : bv;
        const float* gamma = (o == 0) ? ga : gv;
        const float* beta  = (o == 0) ? ta : tv;
        float s = gamma[tid] * rsqrtf(1.f + 1e-5f);
        sS[tid] = s; sC[tid] = bias[tid] * s + beta[tid];
    }

    const __nv_bfloat16* A = xT + (((size_t)o * BB + b) * NNE + (size_t)nt * 128) * CIN;
    const __nv_bfloat16* B = Wc + (size_t)((o == 0) ? 0 : 1) * 65536;

    float acc[4][8][4];
    u32 sA = (u32)__cvta_generic_to_shared(dsm);
    u32 sB = sA + 2 * TILE_B;
    hmma_gemm(sA, sB, A, CIN, B, CIN, CIN, tid, acc);

    __nv_bfloat16* dst = ft + (size_t)o * (size_t)BB * NNE * MIDC
                            + ((size_t)b * NNE + (size_t)nt * 128) * MIDC;
#pragma unroll
    for (int mf = 0; mf < 4; mf++)
#pragma unroll
        for (int nf = 0; nf < 8; nf++)
#pragma unroll
            for (int h = 0; h < 2; h++) {
                int r = wm * 64 + mf * 16 + (lane >> 2) + h * 8;
                int c = wn * 64 + nf * 8 + ((lane & 3) << 1);
                float y0 = fmaxf(acc[mf][nf][h * 2]     * sS[c]     + sC[c],     0.f);
                float y1 = fmaxf(acc[mf][nf][h * 2 + 1] * sS[c + 1] + sC[c + 1], 0.f);
                *reinterpret_cast<u32*>(dst + (size_t)r * MIDC + c) = pack_bf16(y0, y1);
            }
}

// g[sel][b][m][n] = Wg·xT^T + bias (fp32). grid (18, BB, 2). rows=m, cols=n.
__global__ __launch_bounds__(128, 2) void k_gconv(
    const __nv_bfloat16* __restrict__ xT, const __nv_bfloat16* __restrict__ Wc,
    const float* __restrict__ bgav, const float* __restrict__ bgah,
    float* __restrict__ g)
{
    extern __shared__ char dsm[];
    int tid = threadIdx.x, lane = tid & 31, wid = tid >> 5;
    int wm = wid & 1, wn = wid >> 1;
    int nt = blockIdx.x, b = blockIdx.y, o = blockIdx.z;

    const __nv_bfloat16* A = Wc + (size_t)(2 + o) * 65536;
    const __nv_bfloat16* B = xT + ((size_t)b * NNE + (size_t)nt * 128) * CIN;

    float acc[4][8][4];
    u32 sA = (u32)__cvta_generic_to_shared(dsm);
    u32 sB = sA + 2 * TILE_B;
    hmma_gemm(sA, sB, A, CIN, B, CIN, CIN, tid, acc);

    const float* bias = (o == 0) ? bgav : bgah;
    float* dst = g + (size_t)(o * BB + b) * MIDC * NNE + (size_t)nt * 128;
#pragma unroll
    for (int mf = 0; mf < 4; mf++)
#pragma unroll
        for (int nf = 0; nf < 8; nf++)
#pragma unroll
            for (int h = 0; h < 2; h++) {
                int r = wm * 64 + mf * 16 + (lane >> 2) + h * 8;
                int c = wn * 64 + nf * 8 + ((lane & 3) << 1);
                float bval = bias[r];
                *reinterpret_cast<float2*>(dst + (size_t)r * NNE + c) =
                    make_float2(acc[mf][nf][h * 2] + bval, acc[mf][nf][h * 2 + 1] + bval);
            }
}

// ET[sel][b][j][i] = exp(scale * fa[j]·fq[i]); Z[sel][b][i] += column sums.
// grid (it 18, jt 18, b + 8*sel). rows=j, cols=i.
__global__ __launch_bounds__(128, 2) void k_score(
    const __nv_bfloat16* __restrict__ ft, __nv_bfloat16* __restrict__ et,
    float* __restrict__ Z)
{
    extern __shared__ char dsm[];
    __shared__ float zs[2][128];
    int tid = threadIdx.x, lane = tid & 31, wid = tid >> 5;
    int wm = wid & 1, wn = wid >> 1;
    int it = blockIdx.x, jt = blockIdx.y;
    int z = blockIdx.z, b = z & 7, sel = z >> 3;

    const __nv_bfloat16* fa = ft + (size_t)b * NNE * MIDC;
    const __nv_bfloat16* fq = ft + (size_t)(1 + sel) * (size_t)BB * NNE * MIDC
                                 + (size_t)b * NNE * MIDC;
    const __nv_bfloat16* A = fa + (size_t)jt * 128 * MIDC;
    const __nv_bfloat16* B = fq + (size_t)it * 128 * MIDC;

    float acc[4][8][4];
    u32 sA = (u32)__cvta_generic_to_shared(dsm);
    u32 sB = sA + 2 * TILE_B;
    hmma_gemm(sA, sB, A, MIDC, B, MIDC, MIDC, tid, acc);

#pragma unroll
    for (int mf = 0; mf < 4; mf++)
#pragma unroll
        for (int nf = 0; nf < 8; nf++)
#pragma unroll
            for (int e = 0; e < 4; e++)
                acc[mf][nf][e] = __expf(acc[mf][nf][e] * SCALE_S);

    __nv_bfloat16* dst = et + ((size_t)(sel * BB + b) * NNE + (size_t)jt * 128) * NNE
                            + (size_t)it * 128;
#pragma unroll
    for (int mf = 0; mf < 4; mf++)
#pragma unroll
        for (int nf = 0; nf < 8; nf++)
#pragma unroll
            for (int h = 0; h < 2; h++) {
                int r = wm * 64 + mf * 16 + (lane >> 2) + h * 8;
                int c = wn * 64 + nf * 8 + ((lane & 3) << 1);
                *reinterpret_cast<u32*>(dst + (size_t)r * NNE + c) =
                    pack_bf16(acc[mf][nf][h * 2], acc[mf][nf][h * 2 + 1]);
            }

    // column sums: reduce over rows (mf, h, lane>>2), leave per-column partials
#pragma unroll
    for (int nf = 0; nf < 8; nf++) {
        float s0 = 0.f, s1 = 0.f;
#pragma unroll
        for (int mf = 0; mf < 4; mf++) {
            s0 += acc[mf][nf][0] + acc[mf][nf][2];
            s1 += acc[mf][nf][1] + acc[mf][nf][3];
        }
#pragma unroll
        for (int off = 4; off < 32; off <<= 1) {
            s0 += __shfl_xor_sync(0xffffffffu, s0, off);
            s1 += __shfl_xor_sync(0xffffffffu, s1, off);
        }
        if (lane < 4) {
            int c = wn * 64 + nf * 8 + lane * 2;
            zs[wm][c] = s0;
            zs[wm][c + 1] = s1;
        }
    }
    __syncthreads();
    atomicAdd(&Z[(size_t)(sel * BB + b) * NNE + (size_t)it * 128 + tid],
              zs[0][tid] + zs[1][tid]);
}

// oT[sel][b][j][m] = sum_i ET[j][i]·gn[m][i]. grid (jt 18, 1, b+8*sel). rows=j, cols=m.
__global__ __launch_bounds__(128, 2) void k_ogemm(
    const __nv_bfloat16* __restrict__ et, const __nv_bfloat16* __restrict__ gn,
    __nv_bfloat16* __restrict__ oT)
{
    extern __shared__ char dsm[];
    int tid = threadIdx.x, lane = tid & 31, wid = tid >> 5;
    int wm = wid & 1, wn = wid >> 1;
    int jt = blockIdx.x;
    int z = blockIdx.z, b = z & 7, sel = z >> 3;

    const __nv_bfloat16* A = et + ((size_t)(sel * BB + b) * NNE + (size_t)jt * 128) * NNE;
    const __nv_bfloat16* B = gn + (size_t)(sel * BB + b) * MIDC * NNE;

    float acc[4][8][4];
    u32 sA = (u32)__cvta_generic_to_shared(dsm);
    u32 sB = sA + 2 * TILE_B;
    hmma_gemm(sA, sB, A, NNE, B, NNE, NNE, tid, acc);

    __nv_bfloat16* dst = oT + ((size_t)(sel * BB + b) * NNE + (size_t)jt * 128) * MIDC;
#pragma unroll
    for (int mf = 0; mf < 4; mf++)
#pragma unroll
        for (int nf = 0; nf < 8; nf++)
#pragma unroll
            for (int h = 0; h < 2; h++) {
                int r = wm * 64 + mf * 16 + (lane >> 2) + h * 8;
                int c = wn * 64 + nf * 8 + ((lane & 3) << 1);
                *reinterpret_cast<u32*>(dst + (size_t)r * MIDC + c) =
                    pack_bf16(acc[mf][nf][h * 2], acc[mf][nf][h * 2 + 1]);
            }
}

// out[sel][b][cout][n] = Wf·oT^T + bias + x. grid (nt 18, ct 4, b+8*sel). rows=cout, cols=n.
__global__ __launch_bounds__(128, 2) void k_outconv(
    const __nv_bfloat16* __restrict__ Wc, const __nv_bfloat16* __restrict__ oT,
    const float* __restrict__ bfav, const float* __restrict__ bfah,
    const float* __restrict__ x,
    float* __restrict__ out_v, float* __restrict__ out_h)
{
    extern __shared__ char dsm[];
    int tid = threadIdx.x, lane = tid & 31, wid = tid >> 5;
    int wm = wid & 1, wn = wid >> 1;
    int nt = blockIdx.x, ct = blockIdx.y;
    int z = blockIdx.z, b = z & 7, sel = z >> 3;

    const __nv_bfloat16* A = Wc + (size_t)(4 + sel) * 65536 + (size_t)ct * 128 * MIDC;
    const __nv_bfloat16* B = oT + ((size_t)(sel * BB + b) * NNE + (size_t)nt * 128) * MIDC;

    float acc[4][8][4];
    u32 sA = (u32)__cvta_generic_to_shared(dsm);
    u32 sB = sA + 2 * TILE_B;
    hmma_gemm(sA, sB, A, MIDC, B, MIDC, MIDC, tid, acc);

    const float* bias = (sel == 0) ? bfav : bfah;
    float* outp = (sel == 0) ? out_v : out_h;
#pragma unroll
    for (int mf = 0; mf < 4; mf++)
#pragma unroll
        for (int nf = 0; nf < 8; nf++)
#pragma unroll
            for (int h = 0; h < 2; h++) {
                int r = wm * 64 + mf * 16 + (lane >> 2) + h * 8;
                int c = wn * 64 + nf * 8 + ((lane & 3) << 1);
                int cout = ct * 128 + r;
                size_t base = ((size_t)b * CIN + cout) * NNE + (size_t)nt * 128 + c;
                float2 xv = *reinterpret_cast<const float2*>(x + base);
                float bval = bias[cout];
                *reinterpret_cast<float2*>(outp + base) =
                    make_float2(acc[mf][nf][h * 2] + bval + xv.x,
                                acc[mf][nf][h * 2 + 1] + bval + xv.y);
            }
}

// ============================================================================
extern "C" void kernel_launch(void* const* d_in, const int* in_sizes, int n_in,
                              void* d_out, int out_size)
{
    (void)in_sizes; (void)n_in; (void)out_size;

    const float* x    = (const float*)d_in[0];
    const float* x_h  = (const float*)d_in[1];
    const float* x_v  = (const float*)d_in[2];
    const float* Wa   = (const float*)d_in[3];
    const float* ba   = (const float*)d_in[4];
    const float* ga   = (const float*)d_in[5];
    const float* ta   = (const float*)d_in[6];
    const float* Wv   = (const float*)d_in[7];
    const float* bv   = (const float*)d_in[8];
    const float* gv   = (const float*)d_in[9];
    const float* tv   = (const float*)d_in[10];
    const float* Wgav = (const float*)d_in[11];
    const float* bgav = (const float*)d_in[12];
    const float* Wgah = (const float*)d_in[13];
    const float* bgah = (const float*)d_in[14];
    const float* Wfav = (const float*)d_in[15];
    const float* bfav = (const float*)d_in[16];
    const float* Wfah = (const float*)d_in[17];
    const float* bfah = (const float*)d_in[18];

    void* sp = nullptr;
    cudaGetSymbolAddress(&sp, d_scratch);
    char* base = (char*)sp;
    __nv_bfloat16* xT = (__nv_bfloat16*)(base + XT_OFF);
    __nv_bfloat16* ft = (__nv_bfloat16*)(base + FT_OFF);
    float*         g  = (float*)(base + G_OFF);
    __nv_bfloat16* gn = (__nv_bfloat16*)(base + GN_OFF);
    __nv_bfloat16* et = (__nv_bfloat16*)(base + ET_OFF);
    float*         Zp = (float*)(base + Z_OFF);
    __nv_bfloat16* oT = (__nv_bfloat16*)(base + OT_OFF);
    __nv_bfloat16* Wc = (__nv_bfloat16*)(base + WC_OFF);

    float* out_h = (float*)d_out;
    float* out_v = out_h + (size_t)BB * CIN * NNE;

    static int attr_done = 0;
    if (!attr_done) {
        cudaFuncSetAttribute(k_fconv,   cudaFuncAttributeMaxDynamicSharedMemorySize, SMEM_DYN);
        cudaFuncSetAttribute(k_gconv,   cudaFuncAttributeMaxDynamicSharedMemorySize, SMEM_DYN);
        cudaFuncSetAttribute(k_score,   cudaFuncAttributeMaxDynamicSharedMemorySize, SMEM_DYN);
        cudaFuncSetAttribute(k_ogemm,   cudaFuncAttributeMaxDynamicSharedMemorySize, SMEM_DYN);
        cudaFuncSetAttribute(k_outconv, cudaFuncAttributeMaxDynamicSharedMemorySize, SMEM_DYN);
        attr_done = 1;
    }

    // prep: transpose x to bf16 [n][c]; weights to bf16; zero Z
    transpose_x<<<dim3(NNE / 32, CIN / 32, 3 * BB), 256>>>(x, x_v, x_h, xT);
    WC6 w = {{ Wa, Wv, Wgav, Wgah, Wfav, Wfah }};
    conv_weights<<<1536, 256>>>(w, Wc, Zp);

    // input convs
    k_fconv<<<dim3(18, BB, 3), 128, SMEM_DYN>>>(xT, Wc, ba, ga, ta, bv, gv, tv, ft);
    k_gconv<<<dim3(18, BB, 2), 128, SMEM_DYN>>>(xT, Wc, bgav, bgah, g);

    // scores: ET = exp(scale*S)^T, Z = per-query sums
    k_score<<<dim3(18, 18, 16), 128, SMEM_DYN>>>(ft, et, Zp);

    // fold 1/Z into g
    gnorm<<<(2 * BB * MIDC * NNE) / 256, 256>>>(g, Zp, gn);

    // oT = ET·gn^T
    k_ogemm<<<dim3(18, 1, 16), 128, SMEM_DYN>>>(et, gn, oT);

    // output convs + residual
    k_outconv<<<dim3(18, 4, 16), 128, SMEM_DYN>>>(Wc, oT, bfav, bfah, x, out_v, out_h);
}

// round 9
// speedup vs baseline: 1.1764x; 1.1764x over previous
#include <cuda_runtime.h>
#include <cuda_bf16.h>
#include <cstdint>

typedef unsigned int u32;
typedef unsigned long long u64;

#define BB   8
#define CIN  512
#define MIDC 128
#define NNE  2304
#define SCALE_S 0.08838834764831845f

// ---------------- scratch layout (bytes) ----------------
#define XT_SZ   ((size_t)3*BB*NNE*CIN*2)
#define FT_ONE  ((size_t)BB*NNE*MIDC*2)
#define G_SZ    ((size_t)2*BB*MIDC*NNE*4)
#define GN_SZ   ((size_t)2*BB*MIDC*NNE*2)
#define ET_SZ   ((size_t)2*BB*NNE*NNE*2)
#define Z_SZ    ((size_t)2*BB*NNE*4)
#define OT_SZ   ((size_t)2*BB*NNE*MIDC*2)
#define WC_SZ   ((size_t)6*65536*2)

#define XT_OFF  0ull
#define FT_OFF  (XT_OFF + XT_SZ)
#define G_OFF   (FT_OFF + 3*FT_ONE)
#define GN_OFF  (G_OFF + G_SZ)
#define ET_OFF  (GN_OFF + GN_SZ)
#define Z_OFF   (ET_OFF + ET_SZ)
#define OT_OFF  (Z_OFF + Z_SZ)
#define WC_OFF  (OT_OFF + OT_SZ)
#define TOTAL_SCRATCH (WC_OFF + WC_SZ)

__device__ __align__(1024) char d_scratch[TOTAL_SCRATCH];

// ---------------- HMMA building blocks ----------------
__device__ __forceinline__ u32 pack_bf16(float lo, float hi) {
    u32 r; asm("cvt.rn.bf16x2.f32 %0, %1, %2;" : "=r"(r) : "f"(hi), "f"(lo)); return r;
}
__device__ __forceinline__ void cpasync16(u32 saddr, const void* g) {
    asm volatile("cp.async.cg.shared.global [%0], [%1], 16;" :: "r"(saddr), "l"(g));
}
#define CP_COMMIT() asm volatile("cp.async.commit_group;" ::: "memory")

__device__ __forceinline__ void ldsm_x4(u32 a, u32& r0, u32& r1, u32& r2, u32& r3) {
    asm volatile("ldmatrix.sync.aligned.m8n8.x4.shared.b16 {%0,%1,%2,%3}, [%4];"
                 : "=r"(r0), "=r"(r1), "=r"(r2), "=r"(r3) : "r"(a));
}
__device__ __forceinline__ void mma16816(float c[4], const u32 a[4], u32 b0, u32 b1) {
    asm volatile("mma.sync.aligned.m16n8k16.row.col.f32.bf16.bf16.f32 "
                 "{%0,%1,%2,%3}, {%4,%5,%6,%7}, {%8,%9}, {%0,%1,%2,%3};"
                 : "+f"(c[0]), "+f"(c[1]), "+f"(c[2]), "+f"(c[3])
                 : "r"(a[0]), "r"(a[1]), "r"(a[2]), "r"(a[3]), "r"(b0), "r"(b1));
}

// Tiles: A 128 rows x 64 bf16 (128 B/row), B 64 rows x 64 bf16.
// Swizzle cc = c ^ (r & 7): conflict-free cp.async stores + ldmatrix reads.
#define BK 64
#define A_TILE_B (128 * BK * 2)   // 16384
#define B_TILE_B (64 * BK * 2)    // 8192

__device__ __forceinline__ u32 sw64(int r, int ch) {
    return (u32)(r * 128 + ((ch ^ (r & 7)) << 4));
}

// 256 threads: A(128 rows): thread -> row tid>>1, 4 chunks
__device__ __forceinline__ void tile_loadA(u32 sdst, const __nv_bfloat16* src,
                                           size_t pitch, int k0, int tid) {
    int r = tid >> 1;
    const char* g = (const char*)(src + (size_t)r * pitch + k0);
#pragma unroll
    for (int i = 0; i < 4; i++) {
        int c = (tid & 1) * 4 + i;
        cpasync16(sdst + sw64(r, c), g + c * 16);
    }
}
// B(64 rows): thread -> row tid>>2, 2 chunks
__device__ __forceinline__ void tile_loadB(u32 sdst, const __nv_bfloat16* src,
                                           size_t pitch, int k0, int tid) {
    int r = tid >> 2;
    const char* g = (const char*)(src + (size_t)r * pitch + k0);
#pragma unroll
    for (int i = 0; i < 2; i++) {
        int c = (tid & 3) * 2 + i;
        cpasync16(sdst + sw64(r, c), g + c * 16);
    }
}

// CTA 128x64 GEMM: acc += A(128 x Kd, k-major) · B(64 x Kd, k-major)^T
// 256 threads, 8 warps 4(M) x 2(N), warp tile 32x32, BK=64 double-buffered.
__device__ __forceinline__ void hmma_gemm(
    u32 sA, u32 sB,
    const __nv_bfloat16* __restrict__ A, size_t pA,
    const __nv_bfloat16* __restrict__ B, size_t pB,
    int Kd, int tid, float acc[2][4][4])
{
#pragma unroll
    for (int i = 0; i < 2; i++)
#pragma unroll
        for (int j = 0; j < 4; j++)
#pragma unroll
            for (int e = 0; e < 4; e++) acc[i][j][e] = 0.f;

    const int lane = tid & 31, wid = tid >> 5;
    const int wm = wid & 3, wn = wid >> 2;

    tile_loadA(sA, A, pA, 0, tid);
    tile_loadB(sB, B, pB, 0, tid);
    CP_COMMIT();

    const int T = Kd / BK;
    for (int t = 0; t < T; t++) {
        const int cur = t & 1;
        if (t + 1 < T) {
            tile_loadA(sA + (cur ^ 1) * A_TILE_B, A, pA, (t + 1) * BK, tid);
            tile_loadB(sB + (cur ^ 1) * B_TILE_B, B, pB, (t + 1) * BK, tid);
            CP_COMMIT();
            asm volatile("cp.async.wait_group 1;" ::: "memory");
        } else {
            asm volatile("cp.async.wait_group 0;" ::: "memory");
        }
        __syncthreads();
        const u32 abuf = sA + cur * A_TILE_B;
        const u32 bbuf = sB + cur * B_TILE_B;
#pragma unroll
        for (int k16 = 0; k16 < 4; k16++) {
            u32 a[2][4];
#pragma unroll
            for (int f = 0; f < 2; f++) {
                int row = wm * 32 + f * 16 + (lane & 15);
                int ch  = k16 * 2 + (lane >> 4);
                ldsm_x4(abuf + sw64(row, ch), a[f][0], a[f][1], a[f][2], a[f][3]);
            }
            u32 b[4][2];
#pragma unroll
            for (int p = 0; p < 2; p++) {
                int row = wn * 32 + p * 16 + ((lane & 16) >> 1) + (lane & 7);
                int ch  = k16 * 2 + ((lane >> 3) & 1);
                ldsm_x4(bbuf + sw64(row, ch), b[2 * p][0], b[2 * p][1],
                        b[2 * p + 1][0], b[2 * p + 1][1]);
            }
#pragma unroll
            for (int mf = 0; mf < 2; mf++)
#pragma unroll
                for (int nf = 0; nf < 4; nf++)
                    mma16816(acc[mf][nf], a[mf], b[nf][0], b[nf][1]);
        }
        __syncthreads();
    }
}

#define SMEM_DYN (2 * A_TILE_B + 2 * B_TILE_B)   // 48 KB

// ============================ SIMT prep ============================
__global__ __launch_bounds__(256) void transpose_x(
    const float* __restrict__ x, const float* __restrict__ x_v,
    const float* __restrict__ x_h, __nv_bfloat16* __restrict__ xT)
{
    __shared__ float t[32][33];
    int z = blockIdx.z, tt = z >> 3, b = z & 7;
    const float* src = (tt == 0) ? x : (tt == 1 ? x_v : x_h);
    int n0 = blockIdx.x * 32, c0 = blockIdx.y * 32;
    int tx = threadIdx.x & 31, ty8 = threadIdx.x >> 5;
#pragma unroll
    for (int i = 0; i < 4; i++)
        t[ty8 + i * 8][tx] = src[((size_t)b * CIN + c0 + ty8 + i * 8) * NNE + n0 + tx];
    __syncthreads();
#pragma unroll
    for (int i = 0; i < 4; i++)
        xT[(((size_t)tt * BB + b) * NNE + n0 + ty8 + i * 8) * CIN + c0 + tx] =
            __float2bfloat16(t[tx][ty8 + i * 8]);
}

struct WC6 { const float* s[6]; };
__global__ __launch_bounds__(256) void conv_weights(WC6 w, __nv_bfloat16* __restrict__ dst,
                                                    float* __restrict__ Z)
{
    int idx = blockIdx.x * 256 + threadIdx.x;
    int t = idx >> 16, i = idx & 65535;
    dst[(size_t)t * 65536 + i] = __float2bfloat16(w.s[t][i]);
    if (idx < 2 * BB * NNE) Z[idx] = 0.f;
}

__global__ __launch_bounds__(256) void gnorm(
    const float* __restrict__ g, const float* __restrict__ Z, __nv_bfloat16* __restrict__ gn)
{
    size_t idx = (size_t)blockIdx.x * 256 + threadIdx.x;
    int n = (int)(idx % NNE);
    size_t sb = idx / ((size_t)NNE * MIDC);
    gn[idx] = __float2bfloat16(g[idx] * __frcp_rn(Z[sb * NNE + n]));
}

// ============================ HMMA kernels ============================
// Common epilogue index map: r = wm*32 + mf*16 + (lane>>2) + h*8 (row in CTA M-tile)
//                            c = wn*32 + nf*8 + (lane&3)*2   (col in CTA N-tile)

// f[o][b][n][m] = relu(BN(xT·W^T)). grid (nt 18 * mt 2, BB, 3). rows=n, cols=m.
__global__ __launch_bounds__(256, 3) void k_fconv(
    const __nv_bfloat16* __restrict__ xT, const __nv_bfloat16* __restrict__ Wc,
    const float* __restrict__ ba, const float* __restrict__ ga, const float* __restrict__ ta,
    const float* __restrict__ bv, const float* __restrict__ gv, const float* __restrict__ tv,
    __nv_bfloat16* __restrict__ ft)
{
    extern __shared__ char dsm[];
    __shared__ float sS[128], sC[128];
    int tid = threadIdx.x, lane = tid & 31, wid = tid >> 5;
    int wm = wid & 3, wn = wid >> 2;
    int nt = blockIdx.x >> 1, mt = blockIdx.x & 1;
    int b = blockIdx.y, o = blockIdx.z;

    if (tid < 128) {
        const float* bias  = (o == 0) ? ba : bv;
        const float* gamma = (o == 0) ? ga : gv;
        const float* beta  = (o == 0) ? ta : tv;
        float s = gamma[tid] * rsqrtf(1.f + 1e-5f);
        sS[tid] = s; sC[tid] = bias[tid] * s + beta[tid];
    }

    const __nv_bfloat16* A = xT + (((size_t)o * BB + b) * NNE + (size_t)nt * 128) * CIN;
    const __nv_bfloat16* B = Wc + (size_t)((o == 0) ? 0 : 1) * 65536 + (size_t)mt * 64 * CIN;

    float acc[2][4][4];
    u32 sA = (u32)__cvta_generic_to_shared(dsm);
    u32 sB = sA + 2 * A_TILE_B;
    hmma_gemm(sA, sB, A, CIN, B, CIN, CIN, tid, acc);

    __nv_bfloat16* dst = ft + (size_t)o * (size_t)BB * NNE * MIDC
                            + ((size_t)b * NNE + (size_t)nt * 128) * MIDC + mt * 64;
#pragma unroll
    for (int mf = 0; mf < 2; mf++)
#pragma unroll
        for (int nf = 0; nf < 4; nf++)
#pragma unroll
            for (int h = 0; h < 2; h++) {
                int r = wm * 32 + mf * 16 + (lane >> 2) + h * 8;
                int c = wn * 32 + nf * 8 + ((lane & 3) << 1);
                int m = mt * 64 + c;
                float y0 = fmaxf(acc[mf][nf][h * 2]     * sS[m]     + sC[m],     0.f);
                float y1 = fmaxf(acc[mf][nf][h * 2 + 1] * sS[m + 1] + sC[m + 1], 0.f);
                *reinterpret_cast<u32*>(dst + (size_t)r * MIDC + c) = pack_bf16(y0, y1);
            }
}

// g[sel][b][m][n] = Wg·xT^T + bias (fp32). grid (nt 36, BB, 2). rows=m(128), cols=n(64).
__global__ __launch_bounds__(256, 3) void k_gconv(
    const __nv_bfloat16* __restrict__ xT, const __nv_bfloat16* __restrict__ Wc,
    const float* __restrict__ bgav, const float* __restrict__ bgah,
    float* __restrict__ g)
{
    extern __shared__ char dsm[];
    int tid = threadIdx.x, lane = tid & 31, wid = tid >> 5;
    int wm = wid & 3, wn = wid >> 2;
    int nt = blockIdx.x, b = blockIdx.y, o = blockIdx.z;

    const __nv_bfloat16* A = Wc + (size_t)(2 + o) * 65536;
    const __nv_bfloat16* B = xT + ((size_t)b * NNE + (size_t)nt * 64) * CIN;

    float acc[2][4][4];
    u32 sA = (u32)__cvta_generic_to_shared(dsm);
    u32 sB = sA + 2 * A_TILE_B;
    hmma_gemm(sA, sB, A, CIN, B, CIN, CIN, tid, acc);

    const float* bias = (o == 0) ? bgav : bgah;
    float* dst = g + (size_t)(o * BB + b) * MIDC * NNE + (size_t)nt * 64;
#pragma unroll
    for (int mf = 0; mf < 2; mf++)
#pragma unroll
        for (int nf = 0; nf < 4; nf++)
#pragma unroll
            for (int h = 0; h < 2; h++) {
                int r = wm * 32 + mf * 16 + (lane >> 2) + h * 8;
                int c = wn * 32 + nf * 8 + ((lane & 3) << 1);
                float bval = bias[r];
                *reinterpret_cast<float2*>(dst + (size_t)r * NNE + c) =
                    make_float2(acc[mf][nf][h * 2] + bval, acc[mf][nf][h * 2 + 1] + bval);
            }
}

// ET[sel][b][j][i] = exp(scale * fa[j]·fq[i]); Z[sel][b][i] += column sums.
// grid (it 36, jt 18, b + 8*sel). rows=j(128), cols=i(64).
__global__ __launch_bounds__(256, 3) void k_score(
    const __nv_bfloat16* __restrict__ ft, __nv_bfloat16* __restrict__ et,
    float* __restrict__ Z)
{
    extern __shared__ char dsm[];
    __shared__ float zs[4][64];
    int tid = threadIdx.x, lane = tid & 31, wid = tid >> 5;
    int wm = wid & 3, wn = wid >> 2;
    int it = blockIdx.x, jt = blockIdx.y;
    int z = blockIdx.z, b = z & 7, sel = z >> 3;

    const __nv_bfloat16* fa = ft + (size_t)b * NNE * MIDC;
    const __nv_bfloat16* fq = ft + (size_t)(1 + sel) * (size_t)BB * NNE * MIDC
                                 + (size_t)b * NNE * MIDC;
    const __nv_bfloat16* A = fa + (size_t)jt * 128 * MIDC;
    const __nv_bfloat16* B = fq + (size_t)it * 64 * MIDC;

    float acc[2][4][4];
    u32 sA = (u32)__cvta_generic_to_shared(dsm);
    u32 sB = sA + 2 * A_TILE_B;
    hmma_gemm(sA, sB, A, MIDC, B, MIDC, MIDC, tid, acc);

#pragma unroll
    for (int mf = 0; mf < 2; mf++)
#pragma unroll
        for (int nf = 0; nf < 4; nf++)
#pragma unroll
            for (int e = 0; e < 4; e++)
                acc[mf][nf][e] = __expf(acc[mf][nf][e] * SCALE_S);

    __nv_bfloat16* dst = et + ((size_t)(sel * BB + b) * NNE + (size_t)jt * 128) * NNE
                            + (size_t)it * 64;
#pragma unroll
    for (int mf = 0; mf < 2; mf++)
#pragma unroll
        for (int nf = 0; nf < 4; nf++)
#pragma unroll
            for (int h = 0; h < 2; h++) {
                int r = wm * 32 + mf * 16 + (lane >> 2) + h * 8;
                int c = wn * 32 + nf * 8 + ((lane & 3) << 1);
                *reinterpret_cast<u32*>(dst + (size_t)r * NNE + c) =
                    pack_bf16(acc[mf][nf][h * 2], acc[mf][nf][h * 2 + 1]);
            }

    // column sums: per warp reduce over mf/h rows and 8 row-groups
#pragma unroll
    for (int nf = 0; nf < 4; nf++) {
        float s0 = 0.f, s1 = 0.f;
#pragma unroll
        for (int mf = 0; mf < 2; mf++) {
            s0 += acc[mf][nf][0] + acc[mf][nf][2];
            s1 += acc[mf][nf][1] + acc[mf][nf][3];
        }
#pragma unroll
        for (int off = 4; off < 32; off <<= 1) {
            s0 += __shfl_xor_sync(0xffffffffu, s0, off);
            s1 += __shfl_xor_sync(0xffffffffu, s1, off);
        }
        if (lane < 4) {
            int c = wn * 32 + nf * 8 + lane * 2;
            zs[wm][c] = s0;
            zs[wm][c + 1] = s1;
        }
    }
    __syncthreads();
    if (tid < 64)
        atomicAdd(&Z[(size_t)(sel * BB + b) * NNE + (size_t)it * 64 + tid],
                  zs[0][tid] + zs[1][tid] + zs[2][tid] + zs[3][tid]);
}

// oT[sel][b][j][m] = sum_i ET[j][i]·gn[m][i]. grid (mt 2, jt 18, b+8*sel). rows=j, cols=m.
__global__ __launch_bounds__(256, 3) void k_ogemm(
    const __nv_bfloat16* __restrict__ et, const __nv_bfloat16* __restrict__ gn,
    __nv_bfloat16* __restrict__ oT)
{
    extern __shared__ char dsm[];
    int tid = threadIdx.x, lane = tid & 31, wid = tid >> 5;
    int wm = wid & 3, wn = wid >> 2;
    int mt = blockIdx.x, jt = blockIdx.y;
    int z = blockIdx.z, b = z & 7, sel = z >> 3;

    const __nv_bfloat16* A = et + ((size_t)(sel * BB + b) * NNE + (size_t)jt * 128) * NNE;
    const __nv_bfloat16* B = gn + (size_t)(sel * BB + b) * MIDC * NNE + (size_t)mt * 64 * NNE;

    float acc[2][4][4];
    u32 sA = (u32)__cvta_generic_to_shared(dsm);
    u32 sB = sA + 2 * A_TILE_B;
    hmma_gemm(sA, sB, A, NNE, B, NNE, NNE, tid, acc);

    __nv_bfloat16* dst = oT + ((size_t)(sel * BB + b) * NNE + (size_t)jt * 128) * MIDC
                            + mt * 64;
#pragma unroll
    for (int mf = 0; mf < 2; mf++)
#pragma unroll
        for (int nf = 0; nf < 4; nf++)
#pragma unroll
            for (int h = 0; h < 2; h++) {
                int r = wm * 32 + mf * 16 + (lane >> 2) + h * 8;
                int c = wn * 32 + nf * 8 + ((lane & 3) << 1);
                *reinterpret_cast<u32*>(dst + (size_t)r * MIDC + c) =
                    pack_bf16(acc[mf][nf][h * 2], acc[mf][nf][h * 2 + 1]);
            }
}

// out[sel][b][cout][n] = Wf·oT^T + bias + x. grid (nt 36, ct 4, b+8*sel). rows=cout(128), cols=n(64).
__global__ __launch_bounds__(256, 3) void k_outconv(
    const __nv_bfloat16* __restrict__ Wc, const __nv_bfloat16* __restrict__ oT,
    const float* __restrict__ bfav, const float* __restrict__ bfah,
    const float* __restrict__ x,
    float* __restrict__ out_v, float* __restrict__ out_h)
{
    extern __shared__ char dsm[];
    int tid = threadIdx.x, lane = tid & 31, wid = tid >> 5;
    int wm = wid & 3, wn = wid >> 2;
    int nt = blockIdx.x, ct = blockIdx.y;
    int z = blockIdx.z, b = z & 7, sel = z >> 3;

    const __nv_bfloat16* A = Wc + (size_t)(4 + sel) * 65536 + (size_t)ct * 128 * MIDC;
    const __nv_bfloat16* B = oT + ((size_t)(sel * BB + b) * NNE + (size_t)nt * 64) * MIDC;

    float acc[2][4][4];
    u32 sA = (u32)__cvta_generic_to_shared(dsm);
    u32 sB = sA + 2 * A_TILE_B;
    hmma_gemm(sA, sB, A, MIDC, B, MIDC, MIDC, tid, acc);

    const float* bias = (sel == 0) ? bfav : bfah;
    float* outp = (sel == 0) ? out_v : out_h;
#pragma unroll
    for (int mf = 0; mf < 2; mf++)
#pragma unroll
        for (int nf = 0; nf < 4; nf++)
#pragma unroll
            for (int h = 0; h < 2; h++) {
                int r = wm * 32 + mf * 16 + (lane >> 2) + h * 8;
                int c = wn * 32 + nf * 8 + ((lane & 3) << 1);
                int cout = ct * 128 + r;
                size_t base = ((size_t)b * CIN + cout) * NNE + (size_t)nt * 64 + c;
                float2 xv = *reinterpret_cast<const float2*>(x + base);
                float bval = bias[cout];
                *reinterpret_cast<float2*>(outp + base) =
                    make_float2(acc[mf][nf][h * 2] + bval + xv.x,
                                acc[mf][nf][h * 2 + 1] + bval + xv.y);
            }
}

// ============================================================================
extern "C" void kernel_launch(void* const* d_in, const int* in_sizes, int n_in,
                              void* d_out, int out_size)
{
    (void)in_sizes; (void)n_in; (void)out_size;

    const float* x    = (const float*)d_in[0];
    const float* x_h  = (const float*)d_in[1];
    const float* x_v  = (const float*)d_in[2];
    const float* Wa   = (const float*)d_in[3];
    const float* ba   = (const float*)d_in[4];
    const float* ga   = (const float*)d_in[5];
    const float* ta   = (const float*)d_in[6];
    const float* Wv   = (const float*)d_in[7];
    const float* bv   = (const float*)d_in[8];
    const float* gv   = (const float*)d_in[9];
    const float* tv   = (const float*)d_in[10];
    const float* Wgav = (const float*)d_in[11];
    const float* bgav = (const float*)d_in[12];
    const float* Wgah = (const float*)d_in[13];
    const float* bgah = (const float*)d_in[14];
    const float* Wfav = (const float*)d_in[15];
    const float* bfav = (const float*)d_in[16];
    const float* Wfah = (const float*)d_in[17];
    const float* bfah = (const float*)d_in[18];

    void* sp = nullptr;
    cudaGetSymbolAddress(&sp, d_scratch);
    char* base = (char*)sp;
    __nv_bfloat16* xT = (__nv_bfloat16*)(base + XT_OFF);
    __nv_bfloat16* ft = (__nv_bfloat16*)(base + FT_OFF);
    float*         g  = (float*)(base + G_OFF);
    __nv_bfloat16* gn = (__nv_bfloat16*)(base + GN_OFF);
    __nv_bfloat16* et = (__nv_bfloat16*)(base + ET_OFF);
    float*         Zp = (float*)(base + Z_OFF);
    __nv_bfloat16* oT = (__nv_bfloat16*)(base + OT_OFF);
    __nv_bfloat16* Wc = (__nv_bfloat16*)(base + WC_OFF);

    float* out_h = (float*)d_out;
    float* out_v = out_h + (size_t)BB * CIN * NNE;

    static int attr_done = 0;
    if (!attr_done) {
        cudaFuncSetAttribute(k_fconv,   cudaFuncAttributeMaxDynamicSharedMemorySize, SMEM_DYN);
        cudaFuncSetAttribute(k_gconv,   cudaFuncAttributeMaxDynamicSharedMemorySize, SMEM_DYN);
        cudaFuncSetAttribute(k_score,   cudaFuncAttributeMaxDynamicSharedMemorySize, SMEM_DYN);
        cudaFuncSetAttribute(k_ogemm,   cudaFuncAttributeMaxDynamicSharedMemorySize, SMEM_DYN);
        cudaFuncSetAttribute(k_outconv, cudaFuncAttributeMaxDynamicSharedMemorySize, SMEM_DYN);
        attr_done = 1;
    }

    // prep: transpose x to bf16 [n][c]; weights to bf16; zero Z
    transpose_x<<<dim3(NNE / 32, CIN / 32, 3 * BB), 256>>>(x, x_v, x_h, xT);
    WC6 w = {{ Wa, Wv, Wgav, Wgah, Wfav, Wfah }};
    conv_weights<<<1536, 256>>>(w, Wc, Zp);

    // input convs
    k_fconv<<<dim3(18 * 2, BB, 3), 256, SMEM_DYN>>>(xT, Wc, ba, ga, ta, bv, gv, tv, ft);
    k_gconv<<<dim3(36, BB, 2), 256, SMEM_DYN>>>(xT, Wc, bgav, bgah, g);

    // scores: ET = exp(scale*S)^T, Z = per-query sums
    k_score<<<dim3(36, 18, 16), 256, SMEM_DYN>>>(ft, et, Zp);

    // fold 1/Z into g
    gnorm<<<(2 * BB * MIDC * NNE) / 256, 256>>>(g, Zp, gn);

    // oT = ET·gn^T
    k_ogemm<<<dim3(2, 18, 16), 256, SMEM_DYN>>>(et, gn, oT);

    // output convs + residual
    k_outconv<<<dim3(36, 4, 16), 256, SMEM_DYN>>>(Wc, oT, bfav, bfah, x, out_v, out_h);
}

// round 10
// speedup vs baseline: 1.2571x; 1.0687x over previous
#include <cuda_runtime.h>
#include <cuda_bf16.h>
#include <cstdint>

typedef unsigned int u32;
typedef unsigned long long u64;

#define BB   8
#define CIN  512
#define MIDC 128
#define NNE  2304
#define SCALE_S 0.08838834764831845f

// ---------------- scratch layout (bytes) ----------------
#define XT_SZ   ((size_t)3*BB*NNE*CIN*2)
#define FT_ONE  ((size_t)BB*NNE*MIDC*2)
#define G_SZ    ((size_t)2*BB*MIDC*NNE*4)
#define GN_SZ   ((size_t)2*BB*MIDC*NNE*2)
#define ET_SZ   ((size_t)2*BB*NNE*NNE*2)
#define Z_SZ    ((size_t)2*BB*NNE*4)
#define OT_SZ   ((size_t)2*BB*NNE*MIDC*2)
#define WC_SZ   ((size_t)6*65536*2)

#define XT_OFF  0ull
#define FT_OFF  (XT_OFF + XT_SZ)
#define G_OFF   (FT_OFF + 3*FT_ONE)
#define GN_OFF  (G_OFF + G_SZ)
#define ET_OFF  (GN_OFF + GN_SZ)
#define Z_OFF   (ET_OFF + ET_SZ)
#define OT_OFF  (Z_OFF + Z_SZ)
#define WC_OFF  (OT_OFF + OT_SZ)
#define TOTAL_SCRATCH (WC_OFF + WC_SZ)

__device__ __align__(1024) char d_scratch[TOTAL_SCRATCH];

// ---------------- HMMA building blocks ----------------
__device__ __forceinline__ u32 pack_bf16(float lo, float hi) {
    u32 r; asm("cvt.rn.bf16x2.f32 %0, %1, %2;" : "=r"(r) : "f"(hi), "f"(lo)); return r;
}
__device__ __forceinline__ void cpasync16(u32 saddr, const void* g) {
    asm volatile("cp.async.cg.shared.global [%0], [%1], 16;" :: "r"(saddr), "l"(g));
}
#define CP_COMMIT() asm volatile("cp.async.commit_group;" ::: "memory")

__device__ __forceinline__ void ldsm_x4(u32 a, u32& r0, u32& r1, u32& r2, u32& r3) {
    asm volatile("ldmatrix.sync.aligned.m8n8.x4.shared.b16 {%0,%1,%2,%3}, [%4];"
                 : "=r"(r0), "=r"(r1), "=r"(r2), "=r"(r3) : "r"(a));
}
__device__ __forceinline__ void mma16816(float c[4], const u32 a[4], u32 b0, u32 b1) {
    asm volatile("mma.sync.aligned.m16n8k16.row.col.f32.bf16.bf16.f32 "
                 "{%0,%1,%2,%3}, {%4,%5,%6,%7}, {%8,%9}, {%0,%1,%2,%3};"
                 : "+f"(c[0]), "+f"(c[1]), "+f"(c[2]), "+f"(c[3])
                 : "r"(a[0]), "r"(a[1]), "r"(a[2]), "r"(a[3]), "r"(b0), "r"(b1));
}

// Tile: 128 rows x 64 bf16 (128 B/row). Swizzle cc = c ^ (r&7) — conflict-free.
#define BK 64
#define TILE_B (128 * BK * 2)   // 16384 bytes
#define NSTAGE 3

__device__ __forceinline__ u32 sw64(int r, int ch) {
    return (u32)(r * 128 + ((ch ^ (r & 7)) << 4));
}

// 256 threads: thread -> row tid>>1, 4 x 16B chunks
__device__ __forceinline__ void tile_load(u32 sdst, const __nv_bfloat16* src,
                                          size_t pitch, int k0, int tid) {
    int r = tid >> 1;
    const char* g = (const char*)(src + (size_t)r * pitch + k0);
#pragma unroll
    for (int i = 0; i < 4; i++) {
        int c = (tid & 1) * 4 + i;
        cpasync16(sdst + sw64(r, c), g + c * 16);
    }
}

// CTA 128x128 GEMM: acc += A(128 x Kd, k-major) · B(128 x Kd, k-major)^T
// 256 threads, 8 warps 2(M) x 4(N), warp tile 64x32.
// 3-stage cp.async pipeline, prefetch distance 2 (covers L2/DRAM latency).
__device__ __forceinline__ void hmma_gemm(
    u32 sA, u32 sB,
    const __nv_bfloat16* __restrict__ A, size_t pA,
    const __nv_bfloat16* __restrict__ B, size_t pB,
    int Kd, int tid, float acc[4][4][4])
{
#pragma unroll
    for (int i = 0; i < 4; i++)
#pragma unroll
        for (int j = 0; j < 4; j++)
#pragma unroll
            for (int e = 0; e < 4; e++) acc[i][j][e] = 0.f;

    const int lane = tid & 31, wid = tid >> 5;
    const int wm = wid & 1, wn = wid >> 1;
    const int T = Kd / BK;

    // prologue: stage 0 and 1
    tile_load(sA, A, pA, 0, tid);
    tile_load(sB, B, pB, 0, tid);
    CP_COMMIT();
    if (T > 1) {
        tile_load(sA + TILE_B, A, pA, BK, tid);
        tile_load(sB + TILE_B, B, pB, BK, tid);
    }
    CP_COMMIT();

    int slot_next = 2 % NSTAGE;   // slot for tile t+2
    for (int t = 0; t < T; t++) {
        asm volatile("cp.async.wait_group 1;" ::: "memory");  // tile t ready
        __syncthreads();   // all warps done reading the slot we are about to refill
        if (t + 2 < T) {
            tile_load(sA + slot_next * TILE_B, A, pA, (t + 2) * BK, tid);
            tile_load(sB + slot_next * TILE_B, B, pB, (t + 2) * BK, tid);
        }
        CP_COMMIT();   // always commit (possibly empty) to keep group accounting exact
        slot_next = (slot_next + 1 == NSTAGE) ? 0 : slot_next + 1;

        const int cur = t % NSTAGE;
        const u32 abuf = sA + cur * TILE_B;
        const u32 bbuf = sB + cur * TILE_B;
#pragma unroll
        for (int k16 = 0; k16 < 4; k16++) {
            u32 a[4][4];
#pragma unroll
            for (int f = 0; f < 4; f++) {
                int row = wm * 64 + f * 16 + (lane & 15);
                int ch  = k16 * 2 + (lane >> 4);
                ldsm_x4(abuf + sw64(row, ch), a[f][0], a[f][1], a[f][2], a[f][3]);
            }
            u32 b[4][2];
#pragma unroll
            for (int p = 0; p < 2; p++) {
                int row = wn * 32 + p * 16 + ((lane & 16) >> 1) + (lane & 7);
                int ch  = k16 * 2 + ((lane >> 3) & 1);
                ldsm_x4(bbuf + sw64(row, ch), b[2 * p][0], b[2 * p][1],
                        b[2 * p + 1][0], b[2 * p + 1][1]);
            }
#pragma unroll
            for (int mf = 0; mf < 4; mf++)
#pragma unroll
                for (int nf = 0; nf < 4; nf++)
                    mma16816(acc[mf][nf], a[mf], b[nf][0], b[nf][1]);
        }
    }
}

#define SMEM_DYN (2 * NSTAGE * TILE_B)   // 96 KB: A[3] + B[3]

// ============================ SIMT prep ============================
__global__ __launch_bounds__(256) void transpose_x(
    const float* __restrict__ x, const float* __restrict__ x_v,
    const float* __restrict__ x_h, __nv_bfloat16* __restrict__ xT)
{
    __shared__ float t[32][33];
    int z = blockIdx.z, tt = z >> 3, b = z & 7;
    const float* src = (tt == 0) ? x : (tt == 1 ? x_v : x_h);
    int n0 = blockIdx.x * 32, c0 = blockIdx.y * 32;
    int tx = threadIdx.x & 31, ty8 = threadIdx.x >> 5;
#pragma unroll
    for (int i = 0; i < 4; i++)
        t[ty8 + i * 8][tx] = src[((size_t)b * CIN + c0 + ty8 + i * 8) * NNE + n0 + tx];
    __syncthreads();
#pragma unroll
    for (int i = 0; i < 4; i++)
        xT[(((size_t)tt * BB + b) * NNE + n0 + ty8 + i * 8) * CIN + c0 + tx] =
            __float2bfloat16(t[tx][ty8 + i * 8]);
}

struct WC6 { const float* s[6]; };
__global__ __launch_bounds__(256) void conv_weights(WC6 w, __nv_bfloat16* __restrict__ dst,
                                                    float* __restrict__ Z)
{
    int idx = blockIdx.x * 256 + threadIdx.x;
    int t = idx >> 16, i = idx & 65535;
    dst[(size_t)t * 65536 + i] = __float2bfloat16(w.s[t][i]);
    if (idx < 2 * BB * NNE) Z[idx] = 0.f;
}

__global__ __launch_bounds__(256) void gnorm(
    const float* __restrict__ g, const float* __restrict__ Z, __nv_bfloat16* __restrict__ gn)
{
    size_t idx = (size_t)blockIdx.x * 256 + threadIdx.x;
    int n = (int)(idx % NNE);
    size_t sb = idx / ((size_t)NNE * MIDC);
    gn[idx] = __float2bfloat16(g[idx] * __frcp_rn(Z[sb * NNE + n]));
}

// ============================ HMMA kernels ============================

// f[o][b][n][m] = relu(BN(xT·W^T)). grid (18, BB, 3). rows=n, cols=m.
__global__ __launch_bounds__(256, 2) void k_fconv(
    const __nv_bfloat16* __restrict__ xT, const __nv_bfloat16* __restrict__ Wc,
    const float* __restrict__ ba, const float* __restrict__ ga, const float* __restrict__ ta,
    const float* __restrict__ bv, const float* __restrict__ gv, const float* __restrict__ tv,
    __nv_bfloat16* __restrict__ ft)
{
    extern __shared__ char dsm[];
    __shared__ float sS[128], sC[128];
    int tid = threadIdx.x, lane = tid & 31, wid = tid >> 5;
    int wm = wid & 1, wn = wid >> 1;
    int nt = blockIdx.x, b = blockIdx.y, o = blockIdx.z;

    if (tid < 128) {
        const float* bias  = (o == 0) ? ba : bv;
        const float* gamma = (o == 0) ? ga : gv;
        const float* beta  = (o == 0) ? ta : tv;
        float s = gamma[tid] * rsqrtf(1.f + 1e-5f);
        sS[tid] = s; sC[tid] = bias[tid] * s + beta[tid];
    }

    const __nv_bfloat16* A = xT + (((size_t)o * BB + b) * NNE + (size_t)nt * 128) * CIN;
    const __nv_bfloat16* B = Wc + (size_t)((o == 0) ? 0 : 1) * 65536;

    float acc[4][4][4];
    u32 sA = (u32)__cvta_generic_to_shared(dsm);
    u32 sB = sA + NSTAGE * TILE_B;
    hmma_gemm(sA, sB, A, CIN, B, CIN, CIN, tid, acc);

    __nv_bfloat16* dst = ft + (size_t)o * (size_t)BB * NNE * MIDC
                            + ((size_t)b * NNE + (size_t)nt * 128) * MIDC;
#pragma unroll
    for (int mf = 0; mf < 4; mf++)
#pragma unroll
        for (int nf = 0; nf < 4; nf++)
#pragma unroll
            for (int h = 0; h < 2; h++) {
                int r = wm * 64 + mf * 16 + (lane >> 2) + h * 8;
                int c = wn * 32 + nf * 8 + ((lane & 3) << 1);
                float y0 = fmaxf(acc[mf][nf][h * 2]     * sS[c]     + sC[c],     0.f);
                float y1 = fmaxf(acc[mf][nf][h * 2 + 1] * sS[c + 1] + sC[c + 1], 0.f);
                *reinterpret_cast<u32*>(dst + (size_t)r * MIDC + c) = pack_bf16(y0, y1);
            }
}

// g[sel][b][m][n] = Wg·xT^T + bias (fp32). grid (18, BB, 2). rows=m, cols=n.
__global__ __launch_bounds__(256, 2) void k_gconv(
    const __nv_bfloat16* __restrict__ xT, const __nv_bfloat16* __restrict__ Wc,
    const float* __restrict__ bgav, const float* __restrict__ bgah,
    float* __restrict__ g)
{
    extern __shared__ char dsm[];
    int tid = threadIdx.x, lane = tid & 31, wid = tid >> 5;
    int wm = wid & 1, wn = wid >> 1;
    int nt = blockIdx.x, b = blockIdx.y, o = blockIdx.z;

    const __nv_bfloat16* A = Wc + (size_t)(2 + o) * 65536;
    const __nv_bfloat16* B = xT + ((size_t)b * NNE + (size_t)nt * 128) * CIN;

    float acc[4][4][4];
    u32 sA = (u32)__cvta_generic_to_shared(dsm);
    u32 sB = sA + NSTAGE * TILE_B;
    hmma_gemm(sA, sB, A, CIN, B, CIN, CIN, tid, acc);

    const float* bias = (o == 0) ? bgav : bgah;
    float* dst = g + (size_t)(o * BB + b) * MIDC * NNE + (size_t)nt * 128;
#pragma unroll
    for (int mf = 0; mf < 4; mf++)
#pragma unroll
        for (int nf = 0; nf < 4; nf++)
#pragma unroll
            for (int h = 0; h < 2; h++) {
                int r = wm * 64 + mf * 16 + (lane >> 2) + h * 8;
                int c = wn * 32 + nf * 8 + ((lane & 3) << 1);
                float bval = bias[r];
                *reinterpret_cast<float2*>(dst + (size_t)r * NNE + c) =
                    make_float2(acc[mf][nf][h * 2] + bval, acc[mf][nf][h * 2 + 1] + bval);
            }
}

// ET[sel][b][j][i] = exp(scale * fa[j]·fq[i]); Z[sel][b][i] += column sums.
// grid (it 18, jt 18, b + 8*sel). rows=j, cols=i.
__global__ __launch_bounds__(256, 2) void k_score(
    const __nv_bfloat16* __restrict__ ft, __nv_bfloat16* __restrict__ et,
    float* __restrict__ Z)
{
    extern __shared__ char dsm[];
    __shared__ float zs[2][128];
    int tid = threadIdx.x, lane = tid & 31, wid = tid >> 5;
    int wm = wid & 1, wn = wid >> 1;
    int it = blockIdx.x, jt = blockIdx.y;
    int z = blockIdx.z, b = z & 7, sel = z >> 3;

    const __nv_bfloat16* fa = ft + (size_t)b * NNE * MIDC;
    const __nv_bfloat16* fq = ft + (size_t)(1 + sel) * (size_t)BB * NNE * MIDC
                                 + (size_t)b * NNE * MIDC;
    const __nv_bfloat16* A = fa + (size_t)jt * 128 * MIDC;
    const __nv_bfloat16* B = fq + (size_t)it * 128 * MIDC;

    float acc[4][4][4];
    u32 sA = (u32)__cvta_generic_to_shared(dsm);
    u32 sB = sA + NSTAGE * TILE_B;
    hmma_gemm(sA, sB, A, MIDC, B, MIDC, MIDC, tid, acc);

#pragma unroll
    for (int mf = 0; mf < 4; mf++)
#pragma unroll
        for (int nf = 0; nf < 4; nf++)
#pragma unroll
            for (int e = 0; e < 4; e++)
                acc[mf][nf][e] = __expf(acc[mf][nf][e] * SCALE_S);

    __nv_bfloat16* dst = et + ((size_t)(sel * BB + b) * NNE + (size_t)jt * 128) * NNE
                            + (size_t)it * 128;
#pragma unroll
    for (int mf = 0; mf < 4; mf++)
#pragma unroll
        for (int nf = 0; nf < 4; nf++)
#pragma unroll
            for (int h = 0; h < 2; h++) {
                int r = wm * 64 + mf * 16 + (lane >> 2) + h * 8;
                int c = wn * 32 + nf * 8 + ((lane & 3) << 1);
                *reinterpret_cast<u32*>(dst + (size_t)r * NNE + c) =
                    pack_bf16(acc[mf][nf][h * 2], acc[mf][nf][h * 2 + 1]);
            }

#pragma unroll
    for (int nf = 0; nf < 4; nf++) {
        float s0 = 0.f, s1 = 0.f;
#pragma unroll
        for (int mf = 0; mf < 4; mf++) {
            s0 += acc[mf][nf][0] + acc[mf][nf][2];
            s1 += acc[mf][nf][1] + acc[mf][nf][3];
        }
#pragma unroll
        for (int off = 4; off < 32; off <<= 1) {
            s0 += __shfl_xor_sync(0xffffffffu, s0, off);
            s1 += __shfl_xor_sync(0xffffffffu, s1, off);
        }
        if (lane < 4) {
            int c = wn * 32 + nf * 8 + lane * 2;
            zs[wm][c] = s0;
            zs[wm][c + 1] = s1;
        }
    }
    __syncthreads();
    if (tid < 128)
        atomicAdd(&Z[(size_t)(sel * BB + b) * NNE + (size_t)it * 128 + tid],
                  zs[0][tid] + zs[1][tid]);
}

// oT[sel][b][j][m] = sum_i ET[j][i]·gn[m][i]. grid (jt 18, 1, b+8*sel). rows=j, cols=m.
__global__ __launch_bounds__(256, 2) void k_ogemm(
    const __nv_bfloat16* __restrict__ et, const __nv_bfloat16* __restrict__ gn,
    __nv_bfloat16* __restrict__ oT)
{
    extern __shared__ char dsm[];
    int tid = threadIdx.x, lane = tid & 31, wid = tid >> 5;
    int wm = wid & 1, wn = wid >> 1;
    int jt = blockIdx.x;
    int z = blockIdx.z, b = z & 7, sel = z >> 3;

    const __nv_bfloat16* A = et + ((size_t)(sel * BB + b) * NNE + (size_t)jt * 128) * NNE;
    const __nv_bfloat16* B = gn + (size_t)(sel * BB + b) * MIDC * NNE;

    float acc[4][4][4];
    u32 sA = (u32)__cvta_generic_to_shared(dsm);
    u32 sB = sA + NSTAGE * TILE_B;
    hmma_gemm(sA, sB, A, NNE, B, NNE, NNE, tid, acc);

    __nv_bfloat16* dst = oT + ((size_t)(sel * BB + b) * NNE + (size_t)jt * 128) * MIDC;
#pragma unroll
    for (int mf = 0; mf < 4; mf++)
#pragma unroll
        for (int nf = 0; nf < 4; nf++)
#pragma unroll
            for (int h = 0; h < 2; h++) {
                int r = wm * 64 + mf * 16 + (lane >> 2) + h * 8;
                int c = wn * 32 + nf * 8 + ((lane & 3) << 1);
                *reinterpret_cast<u32*>(dst + (size_t)r * MIDC + c) =
                    pack_bf16(acc[mf][nf][h * 2], acc[mf][nf][h * 2 + 1]);
            }
}

// out[sel][b][cout][n] = Wf·oT^T + bias + x. grid (nt 18, ct 4, b+8*sel). rows=cout, cols=n.
__global__ __launch_bounds__(256, 2) void k_outconv(
    const __nv_bfloat16* __restrict__ Wc, const __nv_bfloat16* __restrict__ oT,
    const float* __restrict__ bfav, const float* __restrict__ bfah,
    const float* __restrict__ x,
    float* __restrict__ out_v, float* __restrict__ out_h)
{
    extern __shared__ char dsm[];
    int tid = threadIdx.x, lane = tid & 31, wid = tid >> 5;
    int wm = wid & 1, wn = wid >> 1;
    int nt = blockIdx.x, ct = blockIdx.y;
    int z = blockIdx.z, b = z & 7, sel = z >> 3;

    const __nv_bfloat16* A = Wc + (size_t)(4 + sel) * 65536 + (size_t)ct * 128 * MIDC;
    const __nv_bfloat16* B = oT + ((size_t)(sel * BB + b) * NNE + (size_t)nt * 128) * MIDC;

    float acc[4][4][4];
    u32 sA = (u32)__cvta_generic_to_shared(dsm);
    u32 sB = sA + NSTAGE * TILE_B;
    hmma_gemm(sA, sB, A, MIDC, B, MIDC, MIDC, tid, acc);

    const float* bias = (sel == 0) ? bfav : bfah;
    float* outp = (sel == 0) ? out_v : out_h;
#pragma unroll
    for (int mf = 0; mf < 4; mf++)
#pragma unroll
        for (int nf = 0; nf < 4; nf++)
#pragma unroll
            for (int h = 0; h < 2; h++) {
                int r = wm * 64 + mf * 16 + (lane >> 2) + h * 8;
                int c = wn * 32 + nf * 8 + ((lane & 3) << 1);
                int cout = ct * 128 + r;
                size_t base = ((size_t)b * CIN + cout) * NNE + (size_t)nt * 128 + c;
                float2 xv = *reinterpret_cast<const float2*>(x + base);
                float bval = bias[cout];
                *reinterpret_cast<float2*>(outp + base) =
                    make_float2(acc[mf][nf][h * 2] + bval + xv.x,
                                acc[mf][nf][h * 2 + 1] + bval + xv.y);
            }
}

// ============================================================================
extern "C" void kernel_launch(void* const* d_in, const int* in_sizes, int n_in,
                              void* d_out, int out_size)
{
    (void)in_sizes; (void)n_in; (void)out_size;

    const float* x    = (const float*)d_in[0];
    const float* x_h  = (const float*)d_in[1];
    const float* x_v  = (const float*)d_in[2];
    const float* Wa   = (const float*)d_in[3];
    const float* ba   = (const float*)d_in[4];
    const float* ga   = (const float*)d_in[5];
    const float* ta   = (const float*)d_in[6];
    const float* Wv   = (const float*)d_in[7];
    const float* bv   = (const float*)d_in[8];
    const float* gv   = (const float*)d_in[9];
    const float* tv   = (const float*)d_in[10];
    const float* Wgav = (const float*)d_in[11];
    const float* bgav = (const float*)d_in[12];
    const float* Wgah = (const float*)d_in[13];
    const float* bgah = (const float*)d_in[14];
    const float* Wfav = (const float*)d_in[15];
    const float* bfav = (const float*)d_in[16];
    const float* Wfah = (const float*)d_in[17];
    const float* bfah = (const float*)d_in[18];

    void* sp = nullptr;
    cudaGetSymbolAddress(&sp, d_scratch);
    char* base = (char*)sp;
    __nv_bfloat16* xT = (__nv_bfloat16*)(base + XT_OFF);
    __nv_bfloat16* ft = (__nv_bfloat16*)(base + FT_OFF);
    float*         g  = (float*)(base + G_OFF);
    __nv_bfloat16* gn = (__nv_bfloat16*)(base + GN_OFF);
    __nv_bfloat16* et = (__nv_bfloat16*)(base + ET_OFF);
    float*         Zp = (float*)(base + Z_OFF);
    __nv_bfloat16* oT = (__nv_bfloat16*)(base + OT_OFF);
    __nv_bfloat16* Wc = (__nv_bfloat16*)(base + WC_OFF);

    float* out_h = (float*)d_out;
    float* out_v = out_h + (size_t)BB * CIN * NNE;

    static int attr_done = 0;
    if (!attr_done) {
        cudaFuncSetAttribute(k_fconv,   cudaFuncAttributeMaxDynamicSharedMemorySize, SMEM_DYN);
        cudaFuncSetAttribute(k_gconv,   cudaFuncAttributeMaxDynamicSharedMemorySize, SMEM_DYN);
        cudaFuncSetAttribute(k_score,   cudaFuncAttributeMaxDynamicSharedMemorySize, SMEM_DYN);
        cudaFuncSetAttribute(k_ogemm,   cudaFuncAttributeMaxDynamicSharedMemorySize, SMEM_DYN);
        cudaFuncSetAttribute(k_outconv, cudaFuncAttributeMaxDynamicSharedMemorySize, SMEM_DYN);
        attr_done = 1;
    }

    // prep: transpose x to bf16 [n][c]; weights to bf16; zero Z
    transpose_x<<<dim3(NNE / 32, CIN / 32, 3 * BB), 256>>>(x, x_v, x_h, xT);
    WC6 w = {{ Wa, Wv, Wgav, Wgah, Wfav, Wfah }};
    conv_weights<<<1536, 256>>>(w, Wc, Zp);

    // input convs
    k_fconv<<<dim3(18, BB, 3), 256, SMEM_DYN>>>(xT, Wc, ba, ga, ta, bv, gv, tv, ft);
    k_gconv<<<dim3(18, BB, 2), 256, SMEM_DYN>>>(xT, Wc, bgav, bgah, g);

    // scores: ET = exp(scale*S)^T, Z = per-query sums
    k_score<<<dim3(18, 18, 16), 256, SMEM_DYN>>>(ft, et, Zp);

    // fold 1/Z into g
    gnorm<<<(2 * BB * MIDC * NNE) / 256, 256>>>(g, Zp, gn);

    // oT = ET·gn^T
    k_ogemm<<<dim3(18, 1, 16), 256, SMEM_DYN>>>(et, gn, oT);

    // output convs + residual
    k_outconv<<<dim3(18, 4, 16), 256, SMEM_DYN>>>(Wc, oT, bfav, bfah, x, out_v, out_h);
}